// round 15
// baseline (speedup 1.0000x reference)
#include <cuda_runtime.h>
#include <cstdint>

#define TDIM 512
#define NROWS 16384   // B*T = 4*4096

// ---------------- scratch (device globals; no allocation) ----------------
__device__ float g_q[NROWS * TDIM];
__device__ float g_k[NROWS * TDIM];
__device__ float g_v[NROWS * TDIM];
__device__ float g_attn[NROWS * TDIM];
__device__ float g_ctxp[16 * 32 * 64 * 64];   // 16 splits of 32 (b,h) 64x64 partials
__device__ float g_ctx[32 * 64 * 64];
__device__ float g_ksump[16 * 32 * 64];
__device__ float g_ksum[32 * 64];

// ---------------- helpers ----------------
__device__ __forceinline__ unsigned sptr(const void* p) {
    return (unsigned)__cvta_generic_to_shared(p);
}
__device__ __forceinline__ void cp16(void* dst, const void* src) {
    asm volatile("cp.async.cg.shared.global [%0], [%1], 16;\n"
                 :: "r"(sptr(dst)), "l"(src));
}
__device__ __forceinline__ unsigned f2tf32(float f) {
    unsigned u;
    asm("cvt.rna.tf32.f32 %0, %1;" : "=r"(u) : "f"(f));
    return u;
}
__device__ __forceinline__ void mma8(float* c,
    unsigned a0, unsigned a1, unsigned a2, unsigned a3,
    unsigned b0, unsigned b1)
{
    asm volatile("mma.sync.aligned.m16n8k8.row.col.f32.tf32.tf32.f32 "
                 "{%0,%1,%2,%3}, {%4,%5,%6,%7}, {%8,%9}, {%0,%1,%2,%3};"
                 : "+f"(c[0]), "+f"(c[1]), "+f"(c[2]), "+f"(c[3])
                 : "r"(a0), "r"(a1), "r"(a2), "r"(a3), "r"(b0), "r"(b1));
}

// ---------------- tf32 GEMM core: 128x128 tile, K=512, BK=16 double-buffered ----------------
// smem layout in `sm` (floats): As0[128*20] | As1[128*20] | Bs0[128*20] | Bs1[128*20] (= 40960 B)
// 8 warps as 4(M) x 2(N); warp tile 32x64; per warp 2 m16-tiles x 8 n8-tiles.
__device__ __forceinline__ void gemm_load(const float* __restrict__ A,
    const float* __restrict__ W, int m0, int n0, int k0, int tid,
    float* Asd, float* Bsd)
{
#pragma unroll
    for (int j = 0; j < 2; j++) {
        int id  = tid + j * 256;
        int row = id >> 2;
        int seg = (id & 3) << 2;
        cp16(Asd + row * 20 + seg, A + (size_t)(m0 + row) * TDIM + k0 + seg);
        cp16(Bsd + row * 20 + seg, W + (size_t)(n0 + row) * TDIM + k0 + seg);
    }
}

__device__ __forceinline__ void gemm_core(const float* __restrict__ A,
    const float* __restrict__ W, int m0, int n0, int tid,
    float* sm, float (&acc)[2][8][4])
{
    const int lane = tid & 31, wid = tid >> 5;
    const int warp_m = wid >> 1, warp_n = wid & 1;
    const int g = lane >> 2, tg = lane & 3;
    float* As[2] = { sm,        sm + 2560 };
    float* Bs[2] = { sm + 5120, sm + 7680 };

#pragma unroll
    for (int mt = 0; mt < 2; mt++)
#pragma unroll
        for (int nt = 0; nt < 8; nt++)
#pragma unroll
            for (int r = 0; r < 4; r++) acc[mt][nt][r] = 0.f;

    gemm_load(A, W, m0, n0, 0, tid, As[0], Bs[0]);
    asm volatile("cp.async.commit_group;\n" ::: "memory");

#pragma unroll 2
    for (int kt = 0; kt < 32; kt++) {
        if (kt + 1 < 32)
            gemm_load(A, W, m0, n0, (kt + 1) * 16, tid, As[(kt + 1) & 1], Bs[(kt + 1) & 1]);
        asm volatile("cp.async.commit_group;\n" ::: "memory");
        asm volatile("cp.async.wait_group 1;\n" ::: "memory");
        __syncthreads();
        const float* Al = As[kt & 1];
        const float* Bl = Bs[kt & 1];
#pragma unroll
        for (int ks = 0; ks < 2; ks++) {
            const int kb = ks * 8;
            unsigned a[2][4];
#pragma unroll
            for (int mt = 0; mt < 2; mt++) {
                const float* ap = Al + (warp_m * 32 + mt * 16 + g) * 20 + kb + tg;
                a[mt][0] = f2tf32(ap[0]);
                a[mt][1] = f2tf32(ap[160]);      // +8 rows * stride 20
                a[mt][2] = f2tf32(ap[4]);
                a[mt][3] = f2tf32(ap[164]);
            }
#pragma unroll
            for (int nt = 0; nt < 8; nt++) {
                const float* bp2 = Bl + (warp_n * 64 + nt * 8 + g) * 20 + kb + tg;
                unsigned b0 = f2tf32(bp2[0]);
                unsigned b1 = f2tf32(bp2[4]);
                mma8(acc[0][nt], a[0][0], a[0][1], a[0][2], a[0][3], b0, b1);
                mma8(acc[1][nt], a[1][0], a[1][1], a[1][2], a[1][3], b0, b1);
            }
        }
        __syncthreads();
    }
}

// ---------------- Stage A: QKV projection + softmax(q,k) ----------------
__global__ void __launch_bounds__(256) qkv_kernel(
    const float* __restrict__ x,
    const float* __restrict__ Wq, const float* __restrict__ bq,
    const float* __restrict__ Wk, const float* __restrict__ bk,
    const float* __restrict__ Wv, const float* __restrict__ bv)
{
    __shared__ __align__(16) float sm[10240];
    __shared__ float bias_s[128];
    const int tid  = threadIdx.x;
    const int mat  = blockIdx.y >> 2;   // 0=q 1=k 2=v
    const int pair = blockIdx.y & 3;    // head pair (2 heads per 128 cols)
    const int m0 = blockIdx.x * 128;
    const int n0 = pair * 128;
    const float *W, *bias; float* outp;
    if (mat == 0)      { W = Wq; bias = bq; outp = g_q; }
    else if (mat == 1) { W = Wk; bias = bk; outp = g_k; }
    else               { W = Wv; bias = bv; outp = g_v; }
    if (tid < 128) bias_s[tid] = bias[n0 + tid];

    float acc[2][8][4];
    gemm_core(x, W, m0, n0, tid, sm, acc);

    float* Cs = sm;                     // overlay (tiles dead)
    const int lane = tid & 31, wid = tid >> 5;
    const int warp_m = wid >> 1, warp_n = wid & 1;
    const int g = lane >> 2, tg = lane & 3;
    const bool do_sm = (mat < 2);

#pragma unroll
    for (int half = 0; half < 2; half++) {
        if (warp_n == half) {
#pragma unroll
            for (int mt = 0; mt < 2; mt++) {
                const int row = warp_m * 32 + mt * 16 + g;
#pragma unroll
                for (int nt = 0; nt < 8; nt++) {
                    const int col = nt * 8 + tg * 2;
                    const float b0v = bias_s[half * 64 + col];
                    const float b1v = bias_s[half * 64 + col + 1];
                    Cs[row * 66 + col]           = acc[mt][nt][0] + b0v;
                    Cs[row * 66 + col + 1]       = acc[mt][nt][1] + b1v;
                    Cs[(row + 8) * 66 + col]     = acc[mt][nt][2] + b0v;
                    Cs[(row + 8) * 66 + col + 1] = acc[mt][nt][3] + b1v;
                }
            }
        }
        __syncthreads();
        if (do_sm) {   // softmax over the 64 head columns, 2 threads per row
            const int r = tid >> 1;
            float* rowp = Cs + r * 66 + (tid & 1) * 32;
            float mx = -1e30f;
#pragma unroll
            for (int c = 0; c < 32; c++) mx = fmaxf(mx, rowp[c]);
            mx = fmaxf(mx, __shfl_xor_sync(0xffffffffu, mx, 1));
            float s = 0.f;
#pragma unroll
            for (int c = 0; c < 32; c++) { float e = __expf(rowp[c] - mx); rowp[c] = e; s += e; }
            s += __shfl_xor_sync(0xffffffffu, s, 1);
            const float inv = 1.0f / s;
#pragma unroll
            for (int c = 0; c < 32; c++) rowp[c] *= inv;
            __syncthreads();
        }
        const int gcol = n0 + half * 64;
        const int c = tid & 63, r0 = tid >> 6;
#pragma unroll
        for (int i = 0; i < 32; i++) {
            const int r = r0 + i * 4;
            outp[(size_t)(m0 + r) * TDIM + gcol + c] = Cs[r * 66 + c];
        }
        __syncthreads();
    }
}

// ---------------- Stage B: context[d][e] = sum_t k_d v_e (per b,h), + ksum partials ----------------
__global__ void __launch_bounds__(256) ctx_kernel()
{
    const int bh = blockIdx.x, split = blockIdx.y;
    const int b = bh >> 3, h = bh & 7;
    __shared__ __align__(16) float ks[16 * 68];
    __shared__ __align__(16) float vs[16 * 68];
    const int tid = threadIdx.x;
    const int ty = tid >> 4, tx = tid & 15;
    float acc[4][4] = {};
    float ksacc[4] = {};
    const size_t base = ((size_t)(b * 4096 + split * 256)) * TDIM + h * 64;

    for (int tc = 0; tc < 256; tc += 16) {
        __syncthreads();
#pragma unroll
        for (int j = 0; j < 4; j++) {
            const int e = tid + j * 256;
            const int i = e >> 6, c = e & 63;
            const size_t off = base + (size_t)(tc + i) * TDIM + c;
            ks[i * 68 + c] = g_k[off];
            vs[i * 68 + c] = g_v[off];
        }
        __syncthreads();
#pragma unroll
        for (int i = 0; i < 16; i++) {
            const float4 kv  = *(const float4*)(ks + i * 68 + ty * 4);
            const float4 vv4 = *(const float4*)(vs + i * 68 + tx * 4);
            const float kd[4] = { kv.x, kv.y, kv.z, kv.w };
            const float ve[4] = { vv4.x, vv4.y, vv4.z, vv4.w };
#pragma unroll
            for (int aa = 0; aa < 4; aa++) {
                ksacc[aa] += kd[aa];
#pragma unroll
                for (int bb = 0; bb < 4; bb++)
                    acc[aa][bb] += kd[aa] * ve[bb];
            }
        }
    }
    float* dst = g_ctxp + ((size_t)split * 32 + bh) * 4096;
#pragma unroll
    for (int aa = 0; aa < 4; aa++)
#pragma unroll
        for (int bb = 0; bb < 4; bb++)
            dst[(ty * 4 + aa) * 64 + tx * 4 + bb] = acc[aa][bb];
    if (tx == 0) {
#pragma unroll
        for (int aa = 0; aa < 4; aa++)
            g_ksump[split * 2048 + bh * 64 + ty * 4 + aa] = ksacc[aa] * 0.0625f * 16.f; // = ksacc (keep exact)
    }
}

// ---------------- Stage B2: deterministic partial reduction ----------------
__global__ void reduce_kernel()
{
    const int i = blockIdx.x * 256 + threadIdx.x;
    if (i < 131072) {
        float s = 0.f;
#pragma unroll
        for (int p = 0; p < 16; p++) s += g_ctxp[(size_t)p * 131072 + i];
        g_ctx[i] = s;
    }
    if (i < 2048) {
        float s = 0.f;
#pragma unroll
        for (int p = 0; p < 16; p++) s += g_ksump[p * 2048 + i];
        g_ksum[i] = s;
    }
}

// ---------------- Stage C: out = (q @ ctx) * Dinv + q ----------------
__global__ void __launch_bounds__(256) attn_kernel()
{
    const int bh = blockIdx.y;
    const int b = bh >> 3, h = bh & 7;
    const int t0 = blockIdx.x * 64;
    __shared__ __align__(16) float ctx_s[64 * 68];
    __shared__ float q_s[64 * 65];
    __shared__ float ksum_s[64];
    const int tid = threadIdx.x;

#pragma unroll
    for (int j = 0; j < 16; j++) {
        const int e = tid + j * 256;
        ctx_s[(e >> 6) * 68 + (e & 63)] = g_ctx[(size_t)bh * 4096 + e];
    }
    if (tid < 64) ksum_s[tid] = g_ksum[bh * 64 + tid];
    const size_t base = ((size_t)(b * 4096 + t0)) * TDIM + h * 64;
#pragma unroll
    for (int j = 0; j < 16; j++) {
        const int e = tid + j * 256;
        const int r = e >> 6, c = e & 63;
        q_s[r * 65 + c] = g_q[base + (size_t)r * TDIM + c];
    }
    __syncthreads();

    const int r = tid >> 2, eb = (tid & 3) * 16;
    float acc[16] = {};
    float dacc = 0.f;
#pragma unroll 8
    for (int d = 0; d < 64; d++) {
        const float qd = q_s[r * 65 + d];
        dacc += qd * ksum_s[d];
        const float4* cp = (const float4*)(ctx_s + d * 68 + eb);
#pragma unroll
        for (int jj = 0; jj < 4; jj++) {
            const float4 cv = cp[jj];
            acc[jj * 4 + 0] += qd * cv.x;
            acc[jj * 4 + 1] += qd * cv.y;
            acc[jj * 4 + 2] += qd * cv.z;
            acc[jj * 4 + 3] += qd * cv.w;
        }
    }
    const float dinv = 1.0f / dacc;
#pragma unroll
    for (int jj = 0; jj < 16; jj++)
        g_attn[base + (size_t)r * TDIM + eb + jj] = acc[jj] * dinv + q_s[r * 65 + eb + jj];
}

// ---------------- Stage D: output projection ----------------
__global__ void __launch_bounds__(256) proj_kernel(
    const float* __restrict__ Wp, const float* __restrict__ bp,
    float* __restrict__ out)
{
    __shared__ __align__(16) float sm[10240];
    __shared__ float bias_s[128];
    const int tid = threadIdx.x;
    const int m0 = blockIdx.x * 128;
    const int n0 = blockIdx.y * 128;
    if (tid < 128) bias_s[tid] = bp[n0 + tid];

    float acc[2][8][4];
    gemm_core(g_attn, Wp, m0, n0, tid, sm, acc);

    float* Cs = sm;
    const int lane = tid & 31, wid = tid >> 5;
    const int warp_m = wid >> 1, warp_n = wid & 1;
    const int g = lane >> 2, tg = lane & 3;

#pragma unroll
    for (int half = 0; half < 2; half++) {
        if (warp_n == half) {
#pragma unroll
            for (int mt = 0; mt < 2; mt++) {
                const int row = warp_m * 32 + mt * 16 + g;
#pragma unroll
                for (int nt = 0; nt < 8; nt++) {
                    const int col = nt * 8 + tg * 2;
                    const float b0v = bias_s[half * 64 + col];
                    const float b1v = bias_s[half * 64 + col + 1];
                    Cs[row * 66 + col]           = acc[mt][nt][0] + b0v;
                    Cs[row * 66 + col + 1]       = acc[mt][nt][1] + b1v;
                    Cs[(row + 8) * 66 + col]     = acc[mt][nt][2] + b0v;
                    Cs[(row + 8) * 66 + col + 1] = acc[mt][nt][3] + b1v;
                }
            }
        }
        __syncthreads();
        const int gcol = n0 + half * 64;
        const int c = tid & 63, r0 = tid >> 6;
#pragma unroll
        for (int i = 0; i < 32; i++) {
            const int r = r0 + i * 4;
            out[(size_t)(m0 + r) * TDIM + gcol + c] = Cs[r * 66 + c];
        }
        __syncthreads();
    }
}

// ---------------- launch ----------------
extern "C" void kernel_launch(void* const* d_in, const int* in_sizes, int n_in,
                              void* d_out, int out_size)
{
    (void)in_sizes; (void)n_in; (void)out_size;
    const float* x  = (const float*)d_in[0];
    const float* Wq = (const float*)d_in[1];
    const float* bq = (const float*)d_in[2];
    const float* Wk = (const float*)d_in[3];
    const float* bk = (const float*)d_in[4];
    const float* Wv = (const float*)d_in[5];
    const float* bv = (const float*)d_in[6];
    const float* Wp = (const float*)d_in[7];
    const float* bp = (const float*)d_in[8];
    float* out = (float*)d_out;

    qkv_kernel<<<dim3(128, 12), 256>>>(x, Wq, bq, Wk, bk, Wv, bv);
    ctx_kernel<<<dim3(32, 16), 256>>>();
    reduce_kernel<<<512, 256>>>();
    attn_kernel<<<dim3(64, 32), 256>>>();
    proj_kernel<<<dim3(128, 4), 256>>>(Wp, bp, out);
}

// round 16
// speedup vs baseline: 1.2501x; 1.2501x over previous
#include <cuda_runtime.h>
#include <cstdint>

#define TDIM 512
#define NROWS 16384   // B*T = 4*4096

// ---------------- scratch (device globals; no allocation) ----------------
__device__ float g_xr[NROWS * TDIM];          // tf32-rounded x
__device__ float g_wr[4 * TDIM * TDIM];       // tf32-rounded Wq,Wk,Wv,Wp
__device__ float g_q[NROWS * TDIM];
__device__ float g_k[NROWS * TDIM];
__device__ float g_v[NROWS * TDIM];
__device__ float g_attn[NROWS * TDIM];        // tf32-rounded attn output
__device__ float g_ctxp[32 * 32 * 64 * 64];   // 32 partials of 32 (b,h) 64x64
__device__ float g_ctx[32 * 64 * 64];
__device__ float g_ksump[32 * 32 * 64];
__device__ float g_ksum[32 * 64];

// ---------------- helpers ----------------
__device__ __forceinline__ unsigned sptr(const void* p) {
    return (unsigned)__cvta_generic_to_shared(p);
}
__device__ __forceinline__ void cp16(void* dst, const void* src) {
    asm volatile("cp.async.cg.shared.global [%0], [%1], 16;\n"
                 :: "r"(sptr(dst)), "l"(src));
}
__device__ __forceinline__ unsigned f2tf32(float f) {
    unsigned u;
    asm("cvt.rna.tf32.f32 %0, %1;" : "=r"(u) : "f"(f));
    return u;
}
__device__ __forceinline__ float rnd32(float f) {
    return __uint_as_float(f2tf32(f));
}
__device__ __forceinline__ void mma8(float* c,
    unsigned a0, unsigned a1, unsigned a2, unsigned a3,
    unsigned b0, unsigned b1)
{
    asm volatile("mma.sync.aligned.m16n8k8.row.col.f32.tf32.tf32.f32 "
                 "{%0,%1,%2,%3}, {%4,%5,%6,%7}, {%8,%9}, {%0,%1,%2,%3};"
                 : "+f"(c[0]), "+f"(c[1]), "+f"(c[2]), "+f"(c[3])
                 : "r"(a0), "r"(a1), "r"(a2), "r"(a3), "r"(b0), "r"(b1));
}

// ---------------- Stage 0: pre-round inputs to tf32 bits ----------------
__global__ void __launch_bounds__(256) preround_kernel(
    const float* __restrict__ x,
    const float* __restrict__ Wq, const float* __restrict__ Wk,
    const float* __restrict__ Wv, const float* __restrict__ Wp)
{
    const int i = blockIdx.x * 256 + threadIdx.x;   // float4 index
    if (i < 2097152) {                              // x: 8M floats
        float4 v = ((const float4*)x)[i];
        v.x = rnd32(v.x); v.y = rnd32(v.y); v.z = rnd32(v.z); v.w = rnd32(v.w);
        ((float4*)g_xr)[i] = v;
    } else {
        const int j = i - 2097152;                  // weights: 4 x 65536 float4
        const int w = j >> 16;
        const int idx = j & 65535;
        const float* src = (w == 0) ? Wq : (w == 1) ? Wk : (w == 2) ? Wv : Wp;
        float4 v = ((const float4*)src)[idx];
        v.x = rnd32(v.x); v.y = rnd32(v.y); v.z = rnd32(v.z); v.w = rnd32(v.w);
        ((float4*)g_wr)[j] = v;
    }
}

// ---------------- tf32 GEMM core: 128x128 tile, K=512, BK=16 double-buffered ----------------
// Inputs are pre-rounded to tf32 bits -> no cvt in the mainloop.
__device__ __forceinline__ void gemm_load(const float* __restrict__ A,
    const float* __restrict__ W, int m0, int n0, int k0, int tid,
    float* Asd, float* Bsd)
{
#pragma unroll
    for (int j = 0; j < 2; j++) {
        int id  = tid + j * 256;
        int row = id >> 2;
        int seg = (id & 3) << 2;
        cp16(Asd + row * 20 + seg, A + (size_t)(m0 + row) * TDIM + k0 + seg);
        cp16(Bsd + row * 20 + seg, W + (size_t)(n0 + row) * TDIM + k0 + seg);
    }
}

__device__ __forceinline__ void gemm_core(const float* __restrict__ A,
    const float* __restrict__ W, int m0, int n0, int tid,
    float* sm, float (&acc)[2][8][4])
{
    const int lane = tid & 31, wid = tid >> 5;
    const int warp_m = wid >> 1, warp_n = wid & 1;
    const int g = lane >> 2, tg = lane & 3;
    float* As[2] = { sm,        sm + 2560 };
    float* Bs[2] = { sm + 5120, sm + 7680 };

#pragma unroll
    for (int mt = 0; mt < 2; mt++)
#pragma unroll
        for (int nt = 0; nt < 8; nt++)
#pragma unroll
            for (int r = 0; r < 4; r++) acc[mt][nt][r] = 0.f;

    gemm_load(A, W, m0, n0, 0, tid, As[0], Bs[0]);
    asm volatile("cp.async.commit_group;\n" ::: "memory");

#pragma unroll 2
    for (int kt = 0; kt < 32; kt++) {
        if (kt + 1 < 32)
            gemm_load(A, W, m0, n0, (kt + 1) * 16, tid, As[(kt + 1) & 1], Bs[(kt + 1) & 1]);
        asm volatile("cp.async.commit_group;\n" ::: "memory");
        asm volatile("cp.async.wait_group 1;\n" ::: "memory");
        __syncthreads();
        const unsigned* Al = (const unsigned*)As[kt & 1];
        const unsigned* Bl = (const unsigned*)Bs[kt & 1];
#pragma unroll
        for (int ks = 0; ks < 2; ks++) {
            const int kb = ks * 8;
            unsigned a[2][4];
#pragma unroll
            for (int mt = 0; mt < 2; mt++) {
                const unsigned* ap = Al + (warp_m * 32 + mt * 16 + g) * 20 + kb + tg;
                a[mt][0] = ap[0];
                a[mt][1] = ap[160];      // +8 rows * stride 20
                a[mt][2] = ap[4];
                a[mt][3] = ap[164];
            }
#pragma unroll
            for (int nt = 0; nt < 8; nt++) {
                const unsigned* bp2 = Bl + (warp_n * 64 + nt * 8 + g) * 20 + kb + tg;
                unsigned b0 = bp2[0];
                unsigned b1 = bp2[4];
                mma8(acc[0][nt], a[0][0], a[0][1], a[0][2], a[0][3], b0, b1);
                mma8(acc[1][nt], a[1][0], a[1][1], a[1][2], a[1][3], b0, b1);
            }
        }
        __syncthreads();
    }
}

// ---------------- Stage A: QKV projection + softmax(q,k) ----------------
__global__ void __launch_bounds__(256) qkv_kernel(
    const float* __restrict__ bq, const float* __restrict__ bk,
    const float* __restrict__ bv)
{
    __shared__ __align__(16) float sm[10240];
    __shared__ float bias_s[128];
    const int tid  = threadIdx.x;
    const int mat  = blockIdx.y >> 2;   // 0=q 1=k 2=v
    const int pair = blockIdx.y & 3;    // head pair (2 heads per 128 cols)
    const int m0 = blockIdx.x * 128;
    const int n0 = pair * 128;
    const float* bias = (mat == 0) ? bq : (mat == 1) ? bk : bv;
    float* outp      = (mat == 0) ? g_q : (mat == 1) ? g_k : g_v;
    if (tid < 128) bias_s[tid] = bias[n0 + tid];

    float acc[2][8][4];
    gemm_core(g_xr, g_wr + (size_t)mat * TDIM * TDIM, m0, n0, tid, sm, acc);

    float* Cs = sm;                     // overlay (tiles dead)
    const int lane = tid & 31, wid = tid >> 5;
    const int warp_m = wid >> 1, warp_n = wid & 1;
    const int g = lane >> 2, tg = lane & 3;
    const bool do_sm = (mat < 2);

#pragma unroll
    for (int half = 0; half < 2; half++) {
        if (warp_n == half) {
#pragma unroll
            for (int mt = 0; mt < 2; mt++) {
                const int row = warp_m * 32 + mt * 16 + g;
#pragma unroll
                for (int nt = 0; nt < 8; nt++) {
                    const int col = nt * 8 + tg * 2;
                    const float b0v = bias_s[half * 64 + col];
                    const float b1v = bias_s[half * 64 + col + 1];
                    Cs[row * 66 + col]           = acc[mt][nt][0] + b0v;
                    Cs[row * 66 + col + 1]       = acc[mt][nt][1] + b1v;
                    Cs[(row + 8) * 66 + col]     = acc[mt][nt][2] + b0v;
                    Cs[(row + 8) * 66 + col + 1] = acc[mt][nt][3] + b1v;
                }
            }
        }
        __syncthreads();
        if (do_sm) {   // softmax over the 64 head columns, 2 threads per row
            const int r = tid >> 1;
            float* rowp = Cs + r * 66 + (tid & 1) * 32;
            float mx = -1e30f;
#pragma unroll
            for (int c = 0; c < 32; c++) mx = fmaxf(mx, rowp[c]);
            mx = fmaxf(mx, __shfl_xor_sync(0xffffffffu, mx, 1));
            float s = 0.f;
#pragma unroll
            for (int c = 0; c < 32; c++) { float e = __expf(rowp[c] - mx); rowp[c] = e; s += e; }
            s += __shfl_xor_sync(0xffffffffu, s, 1);
            const float inv = 1.0f / s;
#pragma unroll
            for (int c = 0; c < 32; c++) rowp[c] *= inv;
            __syncthreads();
        }
        const int gcol = n0 + half * 64;
        const int c = tid & 63, r0 = tid >> 6;
#pragma unroll
        for (int i = 0; i < 32; i++) {
            const int r = r0 + i * 4;
            outp[(size_t)(m0 + r) * TDIM + gcol + c] = Cs[r * 66 + c];
        }
        __syncthreads();
    }
}

// ---------------- Stage B: context partials, 8x8 register tiles from L2 ----------------
// grid (32 bh, 8 split), 256 threads; 4 sub-groups of 64 threads, each 128 timesteps.
__global__ void __launch_bounds__(256) ctx_kernel()
{
    const int bh = blockIdx.x, split = blockIdx.y;
    const int b = bh >> 3, h = bh & 7;
    const int tid = threadIdx.x;
    const int sub = tid >> 6;
    const int l64 = tid & 63;
    const int ty = l64 >> 3, tx = l64 & 7;     // 8x8 groups of 8x8 outputs
    const int t0 = split * 512 + sub * 128;
    const size_t base = ((size_t)(b * 4096 + t0)) * TDIM + h * 64;

    const float* __restrict__ kp = g_k + base + ty * 8;
    const float* __restrict__ vp = g_v + base + tx * 8;

    float acc[8][8] = {};
    float ksacc[8] = {};

#pragma unroll 2
    for (int t = 0; t < 128; t++) {
        const float4 k0 = *(const float4*)(kp + (size_t)t * TDIM);
        const float4 k1 = *(const float4*)(kp + (size_t)t * TDIM + 4);
        const float4 v0 = *(const float4*)(vp + (size_t)t * TDIM);
        const float4 v1 = *(const float4*)(vp + (size_t)t * TDIM + 4);
        const float kd[8] = { k0.x, k0.y, k0.z, k0.w, k1.x, k1.y, k1.z, k1.w };
        const float ve[8] = { v0.x, v0.y, v0.z, v0.w, v1.x, v1.y, v1.z, v1.w };
#pragma unroll
        for (int a = 0; a < 8; a++) {
            ksacc[a] += kd[a];
#pragma unroll
            for (int e = 0; e < 8; e++) acc[a][e] += kd[a] * ve[e];
        }
    }

    const int p = split * 4 + sub;             // partial index 0..31
    float* dst = g_ctxp + ((size_t)p * 32 + bh) * 4096;
#pragma unroll
    for (int a = 0; a < 8; a++) {
        float4 o0 = { acc[a][0], acc[a][1], acc[a][2], acc[a][3] };
        float4 o1 = { acc[a][4], acc[a][5], acc[a][6], acc[a][7] };
        *(float4*)(dst + (ty * 8 + a) * 64 + tx * 8)     = o0;
        *(float4*)(dst + (ty * 8 + a) * 64 + tx * 8 + 4) = o1;
    }
    if (tx == 0) {
#pragma unroll
        for (int a = 0; a < 8; a++)
            g_ksump[p * 2048 + bh * 64 + ty * 8 + a] = ksacc[a];
    }
}

// ---------------- Stage B2: deterministic partial reduction ----------------
__global__ void __launch_bounds__(256) reduce_kernel()
{
    const int i = blockIdx.x * 256 + threadIdx.x;
    if (i < 131072) {
        float s = 0.f;
#pragma unroll
        for (int p = 0; p < 32; p++) s += g_ctxp[(size_t)p * 131072 + i];
        g_ctx[i] = s;
    }
    if (i < 2048) {
        float s = 0.f;
#pragma unroll
        for (int p = 0; p < 32; p++) s += g_ksump[p * 2048 + i];
        g_ksum[i] = s;
    }
}

// ---------------- Stage C: out = (q @ ctx) * Dinv + q, register-tiled ----------------
// grid (T/128=32, bh=32), 256 threads; thread tile 8 rows x 4 cols.
__global__ void __launch_bounds__(256) attn_kernel()
{
    const int bh = blockIdx.y;
    const int b = bh >> 3, h = bh & 7;
    const int t0 = blockIdx.x * 128;
    __shared__ __align__(16) float q_s[128 * 64];   // 32KB
    __shared__ __align__(16) float ctx_s[64 * 64];  // 16KB
    const int tid = threadIdx.x;
    const int tx = tid & 15;       // col group (4 cols)
    const int ty = tid >> 4;       // row group (8 rows)

    const size_t base = ((size_t)(b * 4096 + t0)) * TDIM + h * 64;
#pragma unroll
    for (int j = 0; j < 4; j++) {
        const int idx = tid + j * 256;
        const int row = idx >> 4, c4 = (idx & 15) * 4;
        *(float4*)(ctx_s + row * 64 + c4) =
            *(const float4*)(g_ctx + (size_t)bh * 4096 + row * 64 + c4);
    }
#pragma unroll
    for (int j = 0; j < 8; j++) {
        const int idx = tid + j * 256;
        const int row = idx >> 4, c4 = (idx & 15) * 4;
        *(float4*)(q_s + row * 64 + c4) =
            *(const float4*)(g_q + base + (size_t)row * TDIM + c4);
    }
    __syncthreads();

    const int r0 = ty * 8, e0 = tx * 4;
    float acc[8][4] = {};
    float dacc[8] = {};
    const float* __restrict__ ksum_p = g_ksum + bh * 64;

#pragma unroll
    for (int d4 = 0; d4 < 64; d4 += 4) {
        const float4 ks4 = *(const float4*)(ksum_p + d4);
        const float* ksf = (const float*)&ks4;
        float4 qv[8];
#pragma unroll
        for (int i = 0; i < 8; i++)
            qv[i] = *(const float4*)(q_s + (r0 + i) * 64 + d4);
#pragma unroll
        for (int dd = 0; dd < 4; dd++) {
            const float4 cv = *(const float4*)(ctx_s + (d4 + dd) * 64 + e0);
#pragma unroll
            for (int i = 0; i < 8; i++) {
                const float qd = ((const float*)&qv[i])[dd];
                acc[i][0] += qd * cv.x;
                acc[i][1] += qd * cv.y;
                acc[i][2] += qd * cv.z;
                acc[i][3] += qd * cv.w;
                dacc[i]   += qd * ksf[dd];
            }
        }
    }

#pragma unroll
    for (int i = 0; i < 8; i++) {
        const float dinv = 1.0f / dacc[i];
        const float4 q4 = *(const float4*)(q_s + (r0 + i) * 64 + e0);
        float4 o;
        o.x = rnd32(acc[i][0] * dinv + q4.x);   // tf32-round for proj input
        o.y = rnd32(acc[i][1] * dinv + q4.y);
        o.z = rnd32(acc[i][2] * dinv + q4.z);
        o.w = rnd32(acc[i][3] * dinv + q4.w);
        *(float4*)(g_attn + base + (size_t)(r0 + i) * TDIM + e0) = o;
    }
}

// ---------------- Stage D: output projection ----------------
__global__ void __launch_bounds__(256) proj_kernel(
    const float* __restrict__ bp, float* __restrict__ out)
{
    __shared__ __align__(16) float sm[10240];
    __shared__ float bias_s[128];
    const int tid = threadIdx.x;
    const int m0 = blockIdx.x * 128;
    const int n0 = blockIdx.y * 128;
    if (tid < 128) bias_s[tid] = bp[n0 + tid];

    float acc[2][8][4];
    gemm_core(g_attn, g_wr + (size_t)3 * TDIM * TDIM, m0, n0, tid, sm, acc);

    float* Cs = sm;
    const int lane = tid & 31, wid = tid >> 5;
    const int warp_m = wid >> 1, warp_n = wid & 1;
    const int g = lane >> 2, tg = lane & 3;

#pragma unroll
    for (int half = 0; half < 2; half++) {
        if (warp_n == half) {
#pragma unroll
            for (int mt = 0; mt < 2; mt++) {
                const int row = warp_m * 32 + mt * 16 + g;
#pragma unroll
                for (int nt = 0; nt < 8; nt++) {
                    const int col = nt * 8 + tg * 2;
                    const float b0v = bias_s[half * 64 + col];
                    const float b1v = bias_s[half * 64 + col + 1];
                    Cs[row * 66 + col]           = acc[mt][nt][0] + b0v;
                    Cs[row * 66 + col + 1]       = acc[mt][nt][1] + b1v;
                    Cs[(row + 8) * 66 + col]     = acc[mt][nt][2] + b0v;
                    Cs[(row + 8) * 66 + col + 1] = acc[mt][nt][3] + b1v;
                }
            }
        }
        __syncthreads();
        const int gcol = n0 + half * 64;
        const int c = tid & 63, r0 = tid >> 6;
#pragma unroll
        for (int i = 0; i < 32; i++) {
            const int r = r0 + i * 4;
            out[(size_t)(m0 + r) * TDIM + gcol + c] = Cs[r * 66 + c];
        }
        __syncthreads();
    }
}

// ---------------- launch ----------------
extern "C" void kernel_launch(void* const* d_in, const int* in_sizes, int n_in,
                              void* d_out, int out_size)
{
    (void)in_sizes; (void)n_in; (void)out_size;
    const float* x  = (const float*)d_in[0];
    const float* Wq = (const float*)d_in[1];
    const float* bq = (const float*)d_in[2];
    const float* Wk = (const float*)d_in[3];
    const float* bk = (const float*)d_in[4];
    const float* Wv = (const float*)d_in[5];
    const float* bv = (const float*)d_in[6];
    const float* Wp = (const float*)d_in[7];
    const float* bp = (const float*)d_in[8];
    float* out = (float*)d_out;

    preround_kernel<<<9216, 256>>>(x, Wq, Wk, Wv, Wp);
    qkv_kernel<<<dim3(128, 12), 256>>>(bq, bk, bv);
    ctx_kernel<<<dim3(32, 8), 256>>>();
    reduce_kernel<<<512, 256>>>();
    attn_kernel<<<dim3(32, 32), 256>>>();
    proj_kernel<<<dim3(128, 4), 256>>>(bp, out);
}